// round 1
// baseline (speedup 1.0000x reference)
#include <cuda_runtime.h>
#include <cstdint>
#include <cstddef>

#define NPTS 4096
#define DIM  64

// Scratch (allocation-free rule: __device__ globals)
__device__ float g_sq[NPTS];
__device__ float g_d2[(size_t)NPTS * NPTS];   // 64 MB, fits in L2
__device__ float g_len[NPTS];                 // 4095 MST edge lengths (+1 pad)

static __device__ __forceinline__ float inf32() { return __int_as_float(0x7f800000); }
static __device__ __forceinline__ unsigned long long umin64(unsigned long long a,
                                                            unsigned long long b) {
    return a < b ? a : b;
}

// ---------------------------------------------------------------------------
// Kernel 1: squared norms
// ---------------------------------------------------------------------------
__global__ void k_sqnorm(const float* __restrict__ p) {
    int i = blockIdx.x * blockDim.x + threadIdx.x;
    if (i >= NPTS) return;
    const float4* r = (const float4*)(p + (size_t)i * DIM);
    float acc = 0.f;
#pragma unroll
    for (int q = 0; q < DIM / 4; q++) {
        float4 v = r[q];
        acc = fmaf(v.x, v.x, acc);
        acc = fmaf(v.y, v.y, acc);
        acc = fmaf(v.z, v.z, acc);
        acc = fmaf(v.w, v.w, acc);
    }
    g_sq[i] = acc;
}

// ---------------------------------------------------------------------------
// Kernel 2: full squared-distance matrix, 32x32 tiles
// d2[i][j] = max(0, sq[i] + sq[j] - 2*dot(p_i, p_j))
// ---------------------------------------------------------------------------
__global__ void k_d2(const float* __restrict__ p) {
    __shared__ float A[32][DIM + 1];   // +1 pad: conflict-free B[tx][k]
    __shared__ float B[32][DIM + 1];
    int tx = threadIdx.x, ty = threadIdx.y;
    int i0 = blockIdx.y * 32, j0 = blockIdx.x * 32;
    int t = ty * 32 + tx;

    for (int e = t; e < 32 * DIM; e += 1024) {
        int r = e >> 6, c = e & 63;
        A[r][c] = p[(size_t)(i0 + r) * DIM + c];
        B[r][c] = p[(size_t)(j0 + r) * DIM + c];
    }
    __syncthreads();

    int i = i0 + ty, j = j0 + tx;
    float dot = 0.f;
#pragma unroll
    for (int k = 0; k < DIM; k++) dot = fmaf(A[ty][k], B[tx][k], dot);
    float v = g_sq[i] + g_sq[j] - 2.f * dot;
    g_d2[(size_t)i * NPTS + j] = fmaxf(v, 0.f);
}

// ---------------------------------------------------------------------------
// Kernel 3: Prim's MST, persistent single block.
// 256 threads x 16 register-resident dist values.
// Per iteration: packed u64 (fbits<<32 | idx) argmin — lowest-index tie-break,
// matching jnp.argmin. One __syncthreads per iteration (double-buffered stage).
// ---------------------------------------------------------------------------
#define TPB 256
#define VPT 16

__global__ void k_prim() {
    __shared__ unsigned long long shw[2][TPB / 32];
    const int tid  = threadIdx.x;
    const int wid  = tid >> 5;
    const int lane = tid & 31;
    const int base = tid * VPT;

    float dist[VPT];
    unsigned int treemask = 0;

    // init: dist = d2 row 0; vertex 0 starts in tree
    const float4* row0 = (const float4*)(g_d2);
#pragma unroll
    for (int q = 0; q < VPT / 4; q++) {
        float4 r = row0[tid * (VPT / 4) + q];
        dist[q * 4 + 0] = r.x;
        dist[q * 4 + 1] = r.y;
        dist[q * 4 + 2] = r.z;
        dist[q * 4 + 3] = r.w;
    }
    if (tid == 0) { dist[0] = inf32(); treemask = 1u; }

    for (int it = 0; it < NPTS - 1; it++) {
        // ---- local argmin (packed key: value bits high, index low) ----
        unsigned long long best = 0xFFFFFFFFFFFFFFFFull;
#pragma unroll
        for (int k = 0; k < VPT; k++) {
            unsigned long long key =
                ((unsigned long long)__float_as_uint(dist[k]) << 32) |
                (unsigned int)(base + k);
            best = umin64(best, key);
        }
        // ---- warp reduce ----
#pragma unroll
        for (int s = 16; s > 0; s >>= 1)
            best = umin64(best, __shfl_down_sync(0xFFFFFFFFu, best, s));

        const int b = it & 1;
        if (lane == 0) shw[b][wid] = best;
        __syncthreads();

        unsigned long long g = shw[b][0];
#pragma unroll
        for (int w = 1; w < TPB / 32; w++) g = umin64(g, shw[b][w]);

        const int   j  = (int)(g & 0xFFFFFFFFull);
        const float w2 = __uint_as_float((unsigned int)(g >> 32));
        if (tid == 0) g_len[it] = sqrtf(w2);

        // ---- dist = min(dist, d2[j]); tree vertices stay +inf ----
        const float4* row = (const float4*)(g_d2 + (size_t)j * NPTS);
#pragma unroll
        for (int q = 0; q < VPT / 4; q++) {
            float4 r = __ldg(&row[tid * (VPT / 4) + q]);
            dist[q * 4 + 0] = fminf(dist[q * 4 + 0], r.x);
            dist[q * 4 + 1] = fminf(dist[q * 4 + 1], r.y);
            dist[q * 4 + 2] = fminf(dist[q * 4 + 2], r.z);
            dist[q * 4 + 3] = fminf(dist[q * 4 + 3], r.w);
        }
        if ((j >> 4) == tid) treemask |= 1u << (j & (VPT - 1));
#pragma unroll
        for (int k = 0; k < VPT; k++)
            if ((treemask >> k) & 1u) dist[k] = inf32();
    }
}

// ---------------------------------------------------------------------------
// Kernel 4: bitonic sort of 4095 lengths (pad 1x +inf to 4096), write output
// ---------------------------------------------------------------------------
__global__ void k_sort(float* __restrict__ out) {
    __shared__ float sh[NPTS];
    const int tid = threadIdx.x;

    for (int m = tid; m < NPTS; m += 1024)
        sh[m] = (m < NPTS - 1) ? g_len[m] : inf32();
    __syncthreads();

    for (int k = 2; k <= NPTS; k <<= 1) {
        for (int j = k >> 1; j > 0; j >>= 1) {
#pragma unroll
            for (int tt = 0; tt < 2; tt++) {
                int t = tid + tt * 1024;            // t in [0, 2048)
                int i = ((t & ~(j - 1)) << 1) | (t & (j - 1));
                int l = i | j;
                float a = sh[i], c = sh[l];
                bool up = (i & k) == 0;
                if ((a > c) == up) { sh[i] = c; sh[l] = a; }
            }
            __syncthreads();
        }
    }
    for (int m = tid; m < NPTS - 1; m += 1024) out[m] = sh[m];
}

// ---------------------------------------------------------------------------
extern "C" void kernel_launch(void* const* d_in, const int* in_sizes, int n_in,
                              void* d_out, int out_size) {
    (void)in_sizes; (void)n_in; (void)out_size;
    const float* points = (const float*)d_in[0];
    float* out = (float*)d_out;

    k_sqnorm<<<NPTS / 256, 256>>>(points);
    k_d2<<<dim3(NPTS / 32, NPTS / 32), dim3(32, 32)>>>(points);
    k_prim<<<1, TPB>>>();
    k_sort<<<1, 1024>>>(out);
}

// round 2
// speedup vs baseline: 17.4063x; 17.4063x over previous
#include <cuda_runtime.h>
#include <cstdint>
#include <cstddef>

#define NPTS 4096
#define DIM  64

// ---------------------------------------------------------------------------
// Scratch (allocation-free rule: __device__ globals)
// ---------------------------------------------------------------------------
__device__ float g_sq[NPTS];
__device__ float g_d2[(size_t)NPTS * NPTS];   // 64 MB, L2-resident
__device__ float g_len[NPTS];                 // MST edge lengths (4095 used)
__device__ unsigned short g_comp[NPTS];       // component id per vertex
__device__ unsigned long long g_best[NPTS];   // per-component best edge key
__device__ int g_par[NPTS];                   // hook/pointer-jump parents
__device__ int g_cnt;                         // edges recorded so far
__device__ int g_done;                        // 1 when MST complete

static __device__ __forceinline__ float inf32() { return __int_as_float(0x7f800000); }
static __device__ __forceinline__ unsigned long long umin64(unsigned long long a,
                                                            unsigned long long b) {
    return a < b ? a : b;
}

// ---------------------------------------------------------------------------
// Kernel 1: squared norms + Boruvka state init
// ---------------------------------------------------------------------------
__global__ void k_init(const float* __restrict__ p) {
    int i = blockIdx.x * blockDim.x + threadIdx.x;
    if (i == 0) { g_cnt = 0; g_done = 0; }
    if (i >= NPTS) return;
    const float4* r = (const float4*)(p + (size_t)i * DIM);
    float acc = 0.f;
#pragma unroll
    for (int q = 0; q < DIM / 4; q++) {
        float4 v = r[q];
        acc = fmaf(v.x, v.x, acc);
        acc = fmaf(v.y, v.y, acc);
        acc = fmaf(v.z, v.z, acc);
        acc = fmaf(v.w, v.w, acc);
    }
    g_sq[i] = acc;
    g_comp[i] = (unsigned short)i;
    g_best[i] = ~0ull;
}

// ---------------------------------------------------------------------------
// Kernel 2: squared-distance matrix, 128x128 tile per block, 8x8 per thread,
// BK=32 (two K phases) to stay under 48KB static smem.
// d2[i][j] = max(0, sq[i] + sq[j] - 2*dot(p_i, p_j))
// ---------------------------------------------------------------------------
__global__ void k_d2(const float* __restrict__ p) {
    __shared__ float As[32][128];   // As[k][i_local]
    __shared__ float Bs[32][128];   // Bs[k][j_local]

    const int t  = threadIdx.x;          // 0..255
    const int tx = t & 15;               // 0..15 -> j fragment
    const int ty = t >> 4;               // 0..15 -> i fragment
    const int i0 = blockIdx.y * 128;
    const int j0 = blockIdx.x * 128;

    const int lr = t >> 1;               // load row 0..127
    const int lc = (t & 1) * 16;         // load col base 0 or 16

    float acc[8][8];
#pragma unroll
    for (int m = 0; m < 8; m++)
#pragma unroll
        for (int n = 0; n < 8; n++) acc[m][n] = 0.f;

#pragma unroll
    for (int k0 = 0; k0 < DIM; k0 += 32) {
#pragma unroll
        for (int q = 0; q < 4; q++) {
            int c = lc + q * 4;
            float4 va = *(const float4*)(p + (size_t)(i0 + lr) * DIM + k0 + c);
            As[c + 0][lr] = va.x; As[c + 1][lr] = va.y;
            As[c + 2][lr] = va.z; As[c + 3][lr] = va.w;
            float4 vb = *(const float4*)(p + (size_t)(j0 + lr) * DIM + k0 + c);
            Bs[c + 0][lr] = vb.x; Bs[c + 1][lr] = vb.y;
            Bs[c + 2][lr] = vb.z; Bs[c + 3][lr] = vb.w;
        }
        __syncthreads();

#pragma unroll
        for (int k = 0; k < 32; k++) {
            float a[8], b[8];
            *(float4*)(a)     = *(const float4*)&As[k][ty * 8];
            *(float4*)(a + 4) = *(const float4*)&As[k][ty * 8 + 4];
            *(float4*)(b)     = *(const float4*)&Bs[k][tx * 8];
            *(float4*)(b + 4) = *(const float4*)&Bs[k][tx * 8 + 4];
#pragma unroll
            for (int m = 0; m < 8; m++)
#pragma unroll
                for (int n = 0; n < 8; n++)
                    acc[m][n] = fmaf(a[m], b[n], acc[m][n]);
        }
        __syncthreads();
    }

    float sqi[8], sqj[8];
#pragma unroll
    for (int m = 0; m < 8; m++) sqi[m] = g_sq[i0 + ty * 8 + m];
#pragma unroll
    for (int n = 0; n < 8; n++) sqj[n] = g_sq[j0 + tx * 8 + n];

#pragma unroll
    for (int m = 0; m < 8; m++) {
        float o[8];
#pragma unroll
        for (int n = 0; n < 8; n++)
            o[n] = fmaxf(sqi[m] + sqj[n] - 2.f * acc[m][n], 0.f);
        float* dst = g_d2 + (size_t)(i0 + ty * 8 + m) * NPTS + j0 + tx * 8;
        *(float4*)(dst)     = *(float4*)(o);
        *(float4*)(dst + 4) = *(float4*)(o + 4);
    }
}

// ---------------------------------------------------------------------------
// Kernel 3: Boruvka min-edge. One warp per row. 128 blocks x 1024 threads.
// Key = (f32 bits << 24) | canonical_edge_id(24b) -> globally unique,
// consistent for both endpoints -> mutual pairs select identical keys.
// ---------------------------------------------------------------------------
__global__ void k_minedge() {
    if (g_done) return;
    __shared__ unsigned short csh[NPTS];
    const int t = threadIdx.x;
    for (int m = t; m < NPTS; m += 1024) csh[m] = g_comp[m];
    __syncthreads();

    const int wid  = t >> 5;
    const int lane = t & 31;
    const int row  = blockIdx.x * 32 + wid;
    const unsigned myc = csh[row];

    const float4*  r4  = (const float4*)(g_d2 + (size_t)row * NPTS);
    const ushort4* c4p = (const ushort4*)csh;

    float    bw  = inf32();
    unsigned bid = 0xFFFFFFu;

#pragma unroll 4
    for (int s = 0; s < 32; s++) {
        const int q = s * 32 + lane;
        float4  d  = r4[q];
        ushort4 cj = c4p[q];
        const int col = q * 4;

        {   unsigned jj = col + 0;
            if (cj.x != myc) {
                unsigned lo = min((unsigned)row, jj), hi = max((unsigned)row, jj);
                unsigned id = (lo << 12) | hi;
                if (d.x < bw || (d.x == bw && id < bid)) { bw = d.x; bid = id; } } }
        {   unsigned jj = col + 1;
            if (cj.y != myc) {
                unsigned lo = min((unsigned)row, jj), hi = max((unsigned)row, jj);
                unsigned id = (lo << 12) | hi;
                if (d.y < bw || (d.y == bw && id < bid)) { bw = d.y; bid = id; } } }
        {   unsigned jj = col + 2;
            if (cj.z != myc) {
                unsigned lo = min((unsigned)row, jj), hi = max((unsigned)row, jj);
                unsigned id = (lo << 12) | hi;
                if (d.z < bw || (d.z == bw && id < bid)) { bw = d.z; bid = id; } } }
        {   unsigned jj = col + 3;
            if (cj.w != myc) {
                unsigned lo = min((unsigned)row, jj), hi = max((unsigned)row, jj);
                unsigned id = (lo << 12) | hi;
                if (d.w < bw || (d.w == bw && id < bid)) { bw = d.w; bid = id; } } }
    }

    unsigned long long key =
        ((unsigned long long)__float_as_uint(bw) << 24) | bid;
#pragma unroll
    for (int s = 16; s > 0; s >>= 1)
        key = umin64(key, __shfl_down_sync(0xFFFFFFFFu, key, s));

    if (lane == 0) atomicMin(&g_best[myc], key);
}

// ---------------------------------------------------------------------------
// Kernel 4: Boruvka hook + record + pointer jump + relabel. Single block.
// ---------------------------------------------------------------------------
__global__ void k_hook() {
    if (g_done) return;
    const int t = threadIdx.x;   // 1024

    for (int c = t; c < NPTS; c += 1024) g_par[c] = c;
    __syncthreads();

    for (int c = t; c < NPTS; c += 1024) {
        unsigned long long k = g_best[c];
        if (k != ~0ull) {
            unsigned id = (unsigned)(k & 0xFFFFFFull);
            int u = (int)(id >> 12), v = (int)(id & 0xFFF);
            int cu = g_comp[u], cv = g_comp[v];
            int other = (cu == c) ? cv : cu;
            bool mutual = (g_best[other] == k);
            if (!mutual || c < other) {
                int idx = atomicAdd(&g_cnt, 1);
                g_len[idx] = sqrtf(__uint_as_float((unsigned)(k >> 24)));
            }
            if (!mutual)          g_par[c] = other;
            else if (c > other)   g_par[c] = other;
        }
    }
    __syncthreads();

#pragma unroll
    for (int it = 0; it < 12; it++) {
        for (int c = t; c < NPTS; c += 1024) g_par[c] = g_par[g_par[c]];
        __syncthreads();
    }

    for (int i = t; i < NPTS; i += 1024)
        g_comp[i] = (unsigned short)g_par[g_comp[i]];
    for (int c = t; c < NPTS; c += 1024) g_best[c] = ~0ull;
    __syncthreads();
    if (t == 0 && g_cnt >= NPTS - 1) g_done = 1;
}

// ---------------------------------------------------------------------------
// Kernel 5: bitonic sort of 4095 lengths (pad one +inf), write output
// ---------------------------------------------------------------------------
__global__ void k_sort(float* __restrict__ out) {
    __shared__ float sh[NPTS];
    const int tid = threadIdx.x;

    for (int m = tid; m < NPTS; m += 1024)
        sh[m] = (m < NPTS - 1) ? g_len[m] : inf32();
    __syncthreads();

    for (int k = 2; k <= NPTS; k <<= 1) {
        for (int j = k >> 1; j > 0; j >>= 1) {
#pragma unroll
            for (int tt = 0; tt < 2; tt++) {
                int t = tid + tt * 1024;            // t in [0, 2048)
                int i = ((t & ~(j - 1)) << 1) | (t & (j - 1));
                int l = i | j;
                float a = sh[i], c = sh[l];
                bool up = (i & k) == 0;
                if ((a > c) == up) { sh[i] = c; sh[l] = a; }
            }
            __syncthreads();
        }
    }
    for (int m = tid; m < NPTS - 1; m += 1024) out[m] = sh[m];
}

// ---------------------------------------------------------------------------
extern "C" void kernel_launch(void* const* d_in, const int* in_sizes, int n_in,
                              void* d_out, int out_size) {
    (void)in_sizes; (void)n_in; (void)out_size;
    const float* points = (const float*)d_in[0];
    float* out = (float*)d_out;

    k_init<<<NPTS / 256, 256>>>(points);
    k_d2<<<dim3(NPTS / 128, NPTS / 128), 256>>>(points);
    for (int r = 0; r < 12; r++) {
        k_minedge<<<NPTS / 32, 1024>>>();
        k_hook<<<1, 1024>>>();
    }
    k_sort<<<1, 1024>>>(out);
}

// round 3
// speedup vs baseline: 19.4889x; 1.1196x over previous
#include <cuda_runtime.h>
#include <cstdint>
#include <cstddef>

#define NPTS 4096
#define DIM  64
#define NBLK 128     // persistent kernel blocks (<= 148 SMs -> co-resident)
#define TPB  1024

// ---------------------------------------------------------------------------
// Scratch (allocation-free rule: __device__ globals)
// ---------------------------------------------------------------------------
__device__ float g_sq[NPTS];
__device__ float g_d2[(size_t)NPTS * NPTS];   // 64 MB, L2-resident
__device__ float g_len[NPTS];                 // MST edge lengths (4095 used)
__device__ unsigned short g_comp[NPTS];       // component id per vertex
__device__ unsigned long long g_best[NPTS];   // per-component best edge key
__device__ int g_cnt;                         // edges recorded
__device__ volatile int g_done;               // 1 when MST complete
__device__ int          g_bar_cnt;            // grid barrier state
__device__ volatile int g_bar_gen;

static __device__ __forceinline__ float inf32() { return __int_as_float(0x7f800000); }
static __device__ __forceinline__ unsigned long long umin64(unsigned long long a,
                                                            unsigned long long b) {
    return a < b ? a : b;
}

// Generation-based software grid barrier (all NBLK blocks co-resident).
static __device__ __forceinline__ void gridbar() {
    __syncthreads();
    if (threadIdx.x == 0) {
        __threadfence();
        int gen = g_bar_gen;
        if (atomicAdd(&g_bar_cnt, 1) == NBLK - 1) {
            g_bar_cnt = 0;
            __threadfence();
            g_bar_gen = gen + 1;
        } else {
            while (g_bar_gen == gen) { }
        }
        __threadfence();
    }
    __syncthreads();
}

// ---------------------------------------------------------------------------
// Kernel 1: squared norms + all state init (incl. barrier, for graph replay)
// ---------------------------------------------------------------------------
__global__ void k_init(const float* __restrict__ p) {
    int i = blockIdx.x * blockDim.x + threadIdx.x;
    if (i == 0) { g_cnt = 0; g_done = 0; g_bar_cnt = 0; g_bar_gen = 0; }
    if (i >= NPTS) return;
    const float4* r = (const float4*)(p + (size_t)i * DIM);
    float acc = 0.f;
#pragma unroll
    for (int q = 0; q < DIM / 4; q++) {
        float4 v = r[q];
        acc = fmaf(v.x, v.x, acc);
        acc = fmaf(v.y, v.y, acc);
        acc = fmaf(v.z, v.z, acc);
        acc = fmaf(v.w, v.w, acc);
    }
    g_sq[i] = acc;
    g_comp[i] = (unsigned short)i;
    g_best[i] = ~0ull;
}

// ---------------------------------------------------------------------------
// Kernel 2: squared-distance matrix, 128x128 tile, 8x8/thread, packed f32x2
// FMAs (FFMA2) -> 2x fp32 throughput. d2 = max(0, sq_i + sq_j - 2 dot).
// ---------------------------------------------------------------------------
__global__ void k_d2(const float* __restrict__ p) {
    __shared__ float As[32][128];   // As[k][i_local]
    __shared__ float Bs[32][128];   // Bs[k][j_local]

    const int t  = threadIdx.x;          // 0..255
    const int tx = t & 15;               // j fragment
    const int ty = t >> 4;               // i fragment
    const int i0 = blockIdx.y * 128;
    const int j0 = blockIdx.x * 128;

    const int lr = t >> 1;               // load row 0..127
    const int lc = (t & 1) * 16;         // load col base 0 or 16

    unsigned long long acc2[8][4];       // 8 i-rows x 4 packed j-pairs
#pragma unroll
    for (int m = 0; m < 8; m++)
#pragma unroll
        for (int n = 0; n < 4; n++) acc2[m][n] = 0ull;

#pragma unroll
    for (int k0 = 0; k0 < DIM; k0 += 32) {
#pragma unroll
        for (int q = 0; q < 4; q++) {
            int c = lc + q * 4;
            float4 va = *(const float4*)(p + (size_t)(i0 + lr) * DIM + k0 + c);
            As[c + 0][lr] = va.x; As[c + 1][lr] = va.y;
            As[c + 2][lr] = va.z; As[c + 3][lr] = va.w;
            float4 vb = *(const float4*)(p + (size_t)(j0 + lr) * DIM + k0 + c);
            Bs[c + 0][lr] = vb.x; Bs[c + 1][lr] = vb.y;
            Bs[c + 2][lr] = vb.z; Bs[c + 3][lr] = vb.w;
        }
        __syncthreads();

#pragma unroll
        for (int k = 0; k < 32; k++) {
            uint4 a0 = *(const uint4*)&As[k][ty * 8];
            uint4 a1 = *(const uint4*)&As[k][ty * 8 + 4];
            unsigned au[8] = {a0.x, a0.y, a0.z, a0.w, a1.x, a1.y, a1.z, a1.w};
            ulonglong2 b0 = *(const ulonglong2*)&Bs[k][tx * 8];
            ulonglong2 b1 = *(const ulonglong2*)&Bs[k][tx * 8 + 4];
            unsigned long long bp[4] = {b0.x, b0.y, b1.x, b1.y};
#pragma unroll
            for (int m = 0; m < 8; m++) {
                unsigned long long ap;
                asm("mov.b64 %0, {%1, %1};" : "=l"(ap) : "r"(au[m]));
#pragma unroll
                for (int n = 0; n < 4; n++)
                    asm("fma.rn.f32x2 %0, %1, %2, %0;"
                        : "+l"(acc2[m][n]) : "l"(ap), "l"(bp[n]));
            }
        }
        __syncthreads();
    }

    float sqi[8], sqj[8];
#pragma unroll
    for (int m = 0; m < 8; m++) sqi[m] = g_sq[i0 + ty * 8 + m];
#pragma unroll
    for (int n = 0; n < 8; n++) sqj[n] = g_sq[j0 + tx * 8 + n];

#pragma unroll
    for (int m = 0; m < 8; m++) {
        float o[8];
#pragma unroll
        for (int n = 0; n < 4; n++) {
            unsigned lo, hi;
            asm("mov.b64 {%0, %1}, %2;" : "=r"(lo), "=r"(hi) : "l"(acc2[m][n]));
            float d0 = __uint_as_float(lo), d1 = __uint_as_float(hi);
            o[2 * n + 0] = fmaxf(sqi[m] + sqj[2 * n + 0] - 2.f * d0, 0.f);
            o[2 * n + 1] = fmaxf(sqi[m] + sqj[2 * n + 1] - 2.f * d1, 0.f);
        }
        float* dst = g_d2 + (size_t)(i0 + ty * 8 + m) * NPTS + j0 + tx * 8;
        *(float4*)(dst)     = *(float4*)(o);
        *(float4*)(dst + 4) = *(float4*)(o + 4);
    }
}

// ---------------------------------------------------------------------------
// Kernel 3: persistent fused Boruvka + sort.
// 128 blocks x 1024 threads. Per round: warp-per-row min-edge scan ->
// grid barrier -> block-0 hook/pointer-jump in SHARED memory -> grid barrier.
// Early break when MST complete. Block 0 then bitonic-sorts and writes out.
// Key = (f32 bits << 24) | canonical_edge_id(24b): globally unique,
// identical from both endpoints -> mutual-pair cycle break by comp id.
// ---------------------------------------------------------------------------
__global__ void __launch_bounds__(TPB, 1) k_mst(float* __restrict__ out) {
    __shared__ int s_mem[4096];   // reused: ushort comp cache / int par / float sort

    const int t    = threadIdx.x;
    const int wid  = t >> 5;
    const int lane = t & 31;
    const int row  = blockIdx.x * 32 + wid;

    for (int r = 0; r < 12; r++) {
        // ---- stage component labels in shared ----
        unsigned short* csh = (unsigned short*)s_mem;
        for (int m = t; m < NPTS; m += TPB) csh[m] = g_comp[m];
        __syncthreads();

        const unsigned myc = csh[row];
        const float4*  r4  = (const float4*)(g_d2 + (size_t)row * NPTS);
        const ushort4* c4p = (const ushort4*)csh;

        float    bw  = inf32();
        unsigned bid = 0xFFFFFFu;

#pragma unroll 4
        for (int s = 0; s < 32; s++) {
            const int q = s * 32 + lane;
            float4  d  = r4[q];
            ushort4 cj = c4p[q];
            const int col = q * 4;
            {   unsigned jj = col + 0;
                if (cj.x != myc) {
                    unsigned lo = min((unsigned)row, jj), hi = max((unsigned)row, jj);
                    unsigned id = (lo << 12) | hi;
                    if (d.x < bw || (d.x == bw && id < bid)) { bw = d.x; bid = id; } } }
            {   unsigned jj = col + 1;
                if (cj.y != myc) {
                    unsigned lo = min((unsigned)row, jj), hi = max((unsigned)row, jj);
                    unsigned id = (lo << 12) | hi;
                    if (d.y < bw || (d.y == bw && id < bid)) { bw = d.y; bid = id; } } }
            {   unsigned jj = col + 2;
                if (cj.z != myc) {
                    unsigned lo = min((unsigned)row, jj), hi = max((unsigned)row, jj);
                    unsigned id = (lo << 12) | hi;
                    if (d.z < bw || (d.z == bw && id < bid)) { bw = d.z; bid = id; } } }
            {   unsigned jj = col + 3;
                if (cj.w != myc) {
                    unsigned lo = min((unsigned)row, jj), hi = max((unsigned)row, jj);
                    unsigned id = (lo << 12) | hi;
                    if (d.w < bw || (d.w == bw && id < bid)) { bw = d.w; bid = id; } } }
        }

        unsigned long long key =
            ((unsigned long long)__float_as_uint(bw) << 24) | bid;
#pragma unroll
        for (int s = 16; s > 0; s >>= 1)
            key = umin64(key, __shfl_down_sync(0xFFFFFFFFu, key, s));
        if (lane == 0) atomicMin(&g_best[myc], key);

        gridbar();

        // ---- hook + record + pointer jump (block 0, shared memory) ----
        if (blockIdx.x == 0) {
            int* par = s_mem;
            for (int c = t; c < NPTS; c += TPB) par[c] = c;
            __syncthreads();

            for (int c = t; c < NPTS; c += TPB) {
                unsigned long long k = g_best[c];
                if (k != ~0ull) {
                    unsigned id = (unsigned)(k & 0xFFFFFFull);
                    int u = (int)(id >> 12), v = (int)(id & 0xFFF);
                    int cu = g_comp[u], cv = g_comp[v];
                    int other = (cu == c) ? cv : cu;
                    bool mutual = (g_best[other] == k);
                    if (!mutual || c < other) {
                        int idx = atomicAdd(&g_cnt, 1);
                        g_len[idx] = sqrtf(__uint_as_float((unsigned)(k >> 24)));
                    }
                    if (!mutual)        par[c] = other;
                    else if (c > other) par[c] = other;
                }
            }
            __syncthreads();

#pragma unroll
            for (int it = 0; it < 12; it++) {
                for (int c = t; c < NPTS; c += TPB) par[c] = par[par[c]];
                __syncthreads();
            }

            for (int i = t; i < NPTS; i += TPB)
                g_comp[i] = (unsigned short)par[g_comp[i]];
            for (int c = t; c < NPTS; c += TPB) g_best[c] = ~0ull;
            __syncthreads();
            if (t == 0 && g_cnt >= NPTS - 1) g_done = 1;
        }

        gridbar();
        if (g_done) break;
    }

    // ---- block 0: bitonic sort of 4095 lengths (pad one +inf), write out ----
    if (blockIdx.x != 0) return;
    __syncthreads();
    float* sh = (float*)s_mem;
    for (int m = t; m < NPTS; m += TPB)
        sh[m] = (m < NPTS - 1) ? g_len[m] : inf32();
    __syncthreads();

    for (int k = 2; k <= NPTS; k <<= 1) {
        for (int j = k >> 1; j > 0; j >>= 1) {
#pragma unroll
            for (int tt = 0; tt < 2; tt++) {
                int u = t + tt * TPB;               // u in [0, 2048)
                int i = ((u & ~(j - 1)) << 1) | (u & (j - 1));
                int l = i | j;
                float a = sh[i], c = sh[l];
                bool up = (i & k) == 0;
                if ((a > c) == up) { sh[i] = c; sh[l] = a; }
            }
            __syncthreads();
        }
    }
    for (int m = t; m < NPTS - 1; m += TPB) out[m] = sh[m];
}

// ---------------------------------------------------------------------------
extern "C" void kernel_launch(void* const* d_in, const int* in_sizes, int n_in,
                              void* d_out, int out_size) {
    (void)in_sizes; (void)n_in; (void)out_size;
    const float* points = (const float*)d_in[0];
    float* out = (float*)d_out;

    k_init<<<NPTS / 256, 256>>>(points);
    k_d2<<<dim3(NPTS / 128, NPTS / 128), 256>>>(points);
    k_mst<<<NBLK, TPB>>>(out);
}

// round 5
// speedup vs baseline: 26.7193x; 1.3710x over previous
#include <cuda_runtime.h>
#include <cstdint>
#include <cstddef>

#define NPTS 4096
#define DIM  64
#define NBLK 128     // persistent blocks (<=148 SMs, 1 block/SM -> co-resident)
#define TPB  1024

// ---------------------------------------------------------------------------
// Scratch (allocation-free rule: __device__ globals)
// ---------------------------------------------------------------------------
__device__ float g_sq[NPTS];
__device__ float g_d2[(size_t)NPTS * NPTS];          // 64 MB, L2-resident
__device__ float g_len[NPTS];                        // MST edge lengths
__device__ unsigned long long g_best[3][NPTS];       // triple-buffered best keys
__device__ int          g_bar_cnt;
__device__ volatile int g_bar_gen;

static __device__ __forceinline__ float inf32() { return __int_as_float(0x7f800000); }
static __device__ __forceinline__ unsigned long long umin64(unsigned long long a,
                                                            unsigned long long b) {
    return a < b ? a : b;
}

static __device__ __forceinline__ void gridbar() {
    __syncthreads();
    if (threadIdx.x == 0) {
        __threadfence();
        int gen = g_bar_gen;
        if (atomicAdd(&g_bar_cnt, 1) == NBLK - 1) {
            g_bar_cnt = 0;
            __threadfence();
            g_bar_gen = gen + 1;
        } else {
            while (g_bar_gen == gen) { }
        }
        __threadfence();
    }
    __syncthreads();
}

// ---------------------------------------------------------------------------
// Kernel 1: warp-per-row squared norms + clear best buffers + barrier reset
// Launch: NPTS warps total = NPTS*32/TPB = 128 blocks x 1024 threads.
// ---------------------------------------------------------------------------
__global__ void k_init(const float* __restrict__ p) {
    const int t   = threadIdx.x;
    const int gt  = blockIdx.x * TPB + t;
    const int row = gt >> 5;
    const int ln  = gt & 31;

    if (gt == 0) { g_bar_cnt = 0; g_bar_gen = 0; }
    if (gt < 3 * NPTS) ((unsigned long long*)g_best)[gt] = ~0ull;

    float2 v = *(const float2*)(p + (size_t)row * DIM + ln * 2);
    float acc = fmaf(v.x, v.x, v.y * v.y);
#pragma unroll
    for (int s = 16; s > 0; s >>= 1)
        acc += __shfl_down_sync(0xFFFFFFFFu, acc, s);
    if (ln == 0) g_sq[row] = acc;
}

// ---------------------------------------------------------------------------
// Kernel 2: d2 matrix (128x128 tile, 8x8/thread, packed f32x2 FMA) with
// FUSED Boruvka round-0 min-edge epilogue (components = singleton vertices):
// per-row min over this block's 128 cols -> atomicMin g_best[0][row].
// Key = (f32bits << 32) | partner_index.
// ---------------------------------------------------------------------------
__global__ void k_d2(const float* __restrict__ p) {
    __shared__ float As[32][128];
    __shared__ float Bs[32][128];

    const int t  = threadIdx.x;          // 0..255
    const int tx = t & 15;
    const int ty = t >> 4;
    const int i0 = blockIdx.y * 128;
    const int j0 = blockIdx.x * 128;

    const int lr = t >> 1;
    const int lc = (t & 1) * 16;

    unsigned long long acc2[8][4];
#pragma unroll
    for (int m = 0; m < 8; m++)
#pragma unroll
        for (int n = 0; n < 4; n++) acc2[m][n] = 0ull;

#pragma unroll
    for (int k0 = 0; k0 < DIM; k0 += 32) {
#pragma unroll
        for (int q = 0; q < 4; q++) {
            int c = lc + q * 4;
            float4 va = *(const float4*)(p + (size_t)(i0 + lr) * DIM + k0 + c);
            As[c + 0][lr] = va.x; As[c + 1][lr] = va.y;
            As[c + 2][lr] = va.z; As[c + 3][lr] = va.w;
            float4 vb = *(const float4*)(p + (size_t)(j0 + lr) * DIM + k0 + c);
            Bs[c + 0][lr] = vb.x; Bs[c + 1][lr] = vb.y;
            Bs[c + 2][lr] = vb.z; Bs[c + 3][lr] = vb.w;
        }
        __syncthreads();

#pragma unroll
        for (int k = 0; k < 32; k++) {
            uint4 a0 = *(const uint4*)&As[k][ty * 8];
            uint4 a1 = *(const uint4*)&As[k][ty * 8 + 4];
            unsigned au[8] = {a0.x, a0.y, a0.z, a0.w, a1.x, a1.y, a1.z, a1.w};
            ulonglong2 b0 = *(const ulonglong2*)&Bs[k][tx * 8];
            ulonglong2 b1 = *(const ulonglong2*)&Bs[k][tx * 8 + 4];
            unsigned long long bp[4] = {b0.x, b0.y, b1.x, b1.y};
#pragma unroll
            for (int m = 0; m < 8; m++) {
                unsigned long long ap;
                asm("mov.b64 %0, {%1, %1};" : "=l"(ap) : "r"(au[m]));
#pragma unroll
                for (int n = 0; n < 4; n++)
                    asm("fma.rn.f32x2 %0, %1, %2, %0;"
                        : "+l"(acc2[m][n]) : "l"(ap), "l"(bp[n]));
            }
        }
        __syncthreads();
    }

    float sqi[8], sqj[8];
#pragma unroll
    for (int m = 0; m < 8; m++) sqi[m] = g_sq[i0 + ty * 8 + m];
#pragma unroll
    for (int n = 0; n < 8; n++) sqj[n] = g_sq[j0 + tx * 8 + n];

#pragma unroll
    for (int m = 0; m < 8; m++) {
        const int row = i0 + ty * 8 + m;
        float o[8];
#pragma unroll
        for (int n = 0; n < 4; n++) {
            unsigned lo, hi;
            asm("mov.b64 {%0, %1}, %2;" : "=r"(lo), "=r"(hi) : "l"(acc2[m][n]));
            float d0 = __uint_as_float(lo), d1 = __uint_as_float(hi);
            o[2 * n + 0] = fmaxf(sqi[m] + sqj[2 * n + 0] - 2.f * d0, 0.f);
            o[2 * n + 1] = fmaxf(sqi[m] + sqj[2 * n + 1] - 2.f * d1, 0.f);
        }
        float* dst = g_d2 + (size_t)row * NPTS + j0 + tx * 8;
        *(float4*)(dst)     = *(float4*)(o);
        *(float4*)(dst + 4) = *(float4*)(o + 4);

        // fused round-0 min-edge
        unsigned long long key = ~0ull;
#pragma unroll
        for (int n = 0; n < 8; n++) {
            unsigned jj = (unsigned)(j0 + tx * 8 + n);
            unsigned long long k2 =
                ((unsigned long long)__float_as_uint(o[n]) << 32) | jj;
            if (jj != (unsigned)row) key = umin64(key, k2);
        }
#pragma unroll
        for (int s = 8; s > 0; s >>= 1)
            key = umin64(key, __shfl_down_sync(0xFFFFFFFFu, key, s, 16));
        if (tx == 0) atomicMin(&g_best[0][row], key);
    }
}

// ---------------------------------------------------------------------------
// Kernel 3: persistent Boruvka + sort. One grid barrier per round.
// Round k: (k>0) scan -> atomicMin into g_best[k%3]; gridbar;
// ALL blocks redundantly hook/pointer-jump/relabel in their own smem
// (identical deterministic result), block 0 records edge lengths,
// each block clears its slice of g_best[(k+2)%3]. Break when m==1.
// ---------------------------------------------------------------------------
__global__ void __launch_bounds__(TPB, 1) k_mst(float* __restrict__ out) {
    __shared__ unsigned short comp[NPTS];   // 8 KB, persistent labels
    __shared__ int par[NPTS];               // 16 KB, also reused as sort buf
    __shared__ int s_m;                     // new component count
    __shared__ int s_cnt;                   // block0 edge counter

    const int t    = threadIdx.x;
    const int wid  = t >> 5;
    const int lane = t & 31;
    const int row  = blockIdx.x * 32 + wid;

    for (int i = t; i < NPTS; i += TPB) comp[i] = (unsigned short)i;
    if (t == 0) s_cnt = 0;
    __syncthreads();

    for (int k = 0; k < 12; k++) {
        if (k > 0) {
            // ---- min-edge scan over row (one warp per row) ----
            const unsigned myc = comp[row];
            const float4*  r4  = (const float4*)(g_d2 + (size_t)row * NPTS);
            const ushort4* c4p = (const ushort4*)comp;

            unsigned long long best = ~0ull;
#pragma unroll 4
            for (int s = 0; s < 32; s++) {
                const int q = s * 32 + lane;
                float4  d  = r4[q];
                ushort4 cj = c4p[q];
                unsigned long long k0 =
                    ((unsigned long long)__float_as_uint(d.x) << 32) | cj.x;
                unsigned long long k1 =
                    ((unsigned long long)__float_as_uint(d.y) << 32) | cj.y;
                unsigned long long k2 =
                    ((unsigned long long)__float_as_uint(d.z) << 32) | cj.z;
                unsigned long long k3 =
                    ((unsigned long long)__float_as_uint(d.w) << 32) | cj.w;
                if (cj.x != myc) best = umin64(best, k0);
                if (cj.y != myc) best = umin64(best, k1);
                if (cj.z != myc) best = umin64(best, k2);
                if (cj.w != myc) best = umin64(best, k3);
            }
#pragma unroll
            for (int s = 16; s > 0; s >>= 1)
                best = umin64(best, __shfl_down_sync(0xFFFFFFFFu, best, s));
            if (lane == 0) atomicMin(&g_best[k % 3][myc], best);

            gridbar();
        }

        // ---- hook (all blocks, redundant & deterministic) ----
        const unsigned long long* B = g_best[k % 3];
        for (int c = t; c < NPTS; c += TPB) par[c] = c;
        if (t == 0) s_m = 0;
        __syncthreads();

        int local_roots = 0;
        for (int c = t; c < NPTS; c += TPB) {
            unsigned long long key = B[c];
            if (key != ~0ull) {
                int other = (int)(unsigned)(key & 0xFFFFFFFFull);
                unsigned long long ko = B[other];
                bool mutual = ((unsigned)(ko & 0xFFFFFFFFull) == (unsigned)c);
                if (!mutual)        par[c] = other;
                else if (c > other) par[c] = other;
                else                local_roots++;
                if (blockIdx.x == 0 && (!mutual || c < other)) {
                    int idx = atomicAdd(&s_cnt, 1);
                    g_len[idx] = sqrtf(__uint_as_float((unsigned)(key >> 32)));
                }
            }
        }
#pragma unroll
        for (int s = 16; s > 0; s >>= 1)
            local_roots += __shfl_down_sync(0xFFFFFFFFu, local_roots, s);
        if (lane == 0 && local_roots) atomicAdd(&s_m, local_roots);
        __syncthreads();

        // pointer jumping (depth <= 4096 -> 12 doublings)
#pragma unroll
        for (int it = 0; it < 12; it++) {
            for (int c = t; c < NPTS; c += TPB) par[c] = par[par[c]];
            __syncthreads();
        }

        // relabel + clear this block's slice of buffer (k+2)%3
        for (int i = t; i < NPTS; i += TPB)
            comp[i] = (unsigned short)par[comp[i]];
        if (t < 32) g_best[(k + 2) % 3][blockIdx.x * 32 + t] = ~0ull;
        __syncthreads();

        if (s_m <= 1) break;
    }

    // ---- block 0: bitonic sort (pad one +inf) and write output ----
    if (blockIdx.x != 0) return;
    __syncthreads();
    float* sh = (float*)par;
    for (int m = t; m < NPTS; m += TPB)
        sh[m] = (m < NPTS - 1) ? g_len[m] : inf32();
    __syncthreads();

    for (int kk = 2; kk <= NPTS; kk <<= 1) {
        for (int j = kk >> 1; j > 0; j >>= 1) {
#pragma unroll
            for (int tt = 0; tt < 2; tt++) {
                int u = t + tt * TPB;
                int i = ((u & ~(j - 1)) << 1) | (u & (j - 1));
                int l = i | j;
                float a = sh[i], c = sh[l];
                bool up = (i & kk) == 0;
                if ((a > c) == up) { sh[i] = c; sh[l] = a; }
            }
            __syncthreads();
        }
    }
    for (int m = t; m < NPTS - 1; m += TPB) out[m] = sh[m];
}

// ---------------------------------------------------------------------------
extern "C" void kernel_launch(void* const* d_in, const int* in_sizes, int n_in,
                              void* d_out, int out_size) {
    (void)in_sizes; (void)n_in; (void)out_size;
    const float* points = (const float*)d_in[0];
    float* out = (float*)d_out;

    k_init<<<NPTS * 32 / TPB, TPB>>>(points);          // 128 blocks x 1024
    k_d2<<<dim3(NPTS / 128, NPTS / 128), 256>>>(points);
    k_mst<<<NBLK, TPB>>>(out);
}